// round 14
// baseline (speedup 1.0000x reference)
#include <cuda_runtime.h>
#include <cuda_fp16.h>
#include <math.h>
#include <stdint.h>

#define LL 16384
#define DD 1024
#define AA 1024

// ---------------- device scratch (static: allocation-free) ----------------
// A: 128 m-blocks x 16 k-chunks, tile 128x64 halves = 16KB, SW128-preswizzled
// B: 8   n-blocks x 16 k-chunks, tile 128x64 halves = 16KB, SW128-preswizzled
__device__ uint4 g_hA[2097152];    // 32 MB
__device__ uint4 g_wB[131072];     // 2 MB
__device__ float g_c[AA];
__device__ float g_beta[LL];
__device__ float g_red[2];         // [0]=max, [1]=sum(exp)

// ---------------- PTX helpers ----------------
__device__ __forceinline__ uint32_t smem_u32(const void* p){
    uint32_t a;
    asm("{ .reg .u64 t; cvta.to.shared.u64 t, %1; cvt.u32.u64 %0, t; }" : "=r"(a) : "l"(p));
    return a;
}
__device__ __forceinline__ uint32_t swz128(uint32_t off){ return off ^ ((off >> 3) & 0x70u); }

__device__ __forceinline__ void mbar_init(uint32_t mbar, uint32_t cnt){
    asm volatile("mbarrier.init.shared.b64 [%0], %1;" :: "r"(mbar), "r"(cnt) : "memory");
}
__device__ __forceinline__ void mbar_expect_tx(uint32_t mbar, uint32_t bytes){
    asm volatile("mbarrier.arrive.expect_tx.shared.b64 _, [%0], %1;"
                 :: "r"(mbar), "r"(bytes) : "memory");
}
__device__ __forceinline__ void mbar_arrive(uint32_t mbar){
    asm volatile("mbarrier.arrive.shared.b64 _, [%0];" :: "r"(mbar) : "memory");
}
__device__ __forceinline__ void mbar_wait(uint32_t mbar, int parity){
    asm volatile(
        "{\n\t.reg .pred P1;\n\t"
        "LAB_WAIT_%=:\n\t"
        "mbarrier.try_wait.parity.acquire.cta.shared::cta.b64 P1, [%0], %1, 0x989680;\n\t"
        "@P1 bra.uni LAB_DONE_%=;\n\t"
        "bra.uni LAB_WAIT_%=;\n\t"
        "LAB_DONE_%=:\n\t}"
        :: "r"(mbar), "r"((uint32_t)parity) : "memory");
}
__device__ __forceinline__ void bulkcp(uint32_t dst, const void* src, uint32_t bytes,
                                       uint32_t mbar){
    asm volatile(
        "cp.async.bulk.shared::cta.global.mbarrier::complete_tx::bytes [%0], [%1], %2, [%3];"
        :: "r"(dst), "l"(src), "r"(bytes), "r"(mbar) : "memory");
}
__device__ __forceinline__ void ldm4(uint32_t* r, uint32_t addr){
    asm volatile("ldmatrix.sync.aligned.m8n8.x4.shared.b16 {%0,%1,%2,%3}, [%4];"
        : "=r"(r[0]), "=r"(r[1]), "=r"(r[2]), "=r"(r[3]) : "r"(addr));
}
__device__ __forceinline__ void mma16816(float* d, const uint32_t* a,
                                         uint32_t b0, uint32_t b1){
    asm volatile(
        "mma.sync.aligned.m16n8k16.row.col.f32.f16.f16.f32 "
        "{%0,%1,%2,%3}, {%4,%5,%6,%7}, {%8,%9}, {%0,%1,%2,%3};"
        : "+f"(d[0]), "+f"(d[1]), "+f"(d[2]), "+f"(d[3])
        : "r"(a[0]), "r"(a[1]), "r"(a[2]), "r"(a[3]), "r"(b0), "r"(b1));
}

__device__ __forceinline__ float fast_tanh(float x){
    float e = __expf(-2.0f * fabsf(x));
    float t = __fdividef(1.0f - e, 1.0f + e);
    return copysignf(t, x);
}

__device__ __forceinline__ uint4 cvt8(const float* src){
    union { __half e[8]; uint4 u; } H;
    #pragma unroll
    for (int q = 0; q < 8; ++q) H.e[q] = __float2half(src[q]);
    return H.u;
}

// ---------------- prep kernel --------------------------------------------
// blocks [0, 8192)     : h -> fp16 tiled+swizzled g_hA (128x64 tiles)
// blocks [8192, 8704)  : W1 -> fp16 tiled+swizzled g_wB
// blocks [8704, 8768)  : zero g_beta
// blocks [8768, 8896)  : c = W2 @ ht + b
__global__ void prep_kernel(const float* __restrict__ h,
                            const float* __restrict__ W,
                            const float* __restrict__ ht,
                            const float* __restrict__ b){
    const int bx = blockIdx.x, tid = threadIdx.x;
    if (bx < 8192){
        int t = bx * 256 + tid;          // 2M chunks of 8 halves
        int m = t >> 7, j = t & 127;
        int kc = j >> 3, jj = j & 7;
        float v[8];
        const float* src = h + (size_t)m * 1024 + kc * 64 + jj * 8;
        #pragma unroll
        for (int q = 0; q < 8; ++q) v[q] = src[q];
        uint4 u16 = cvt8(v);
        size_t doff = ((size_t)((m >> 7) * 16 + kc)) * 16384
                    + swz128((uint32_t)((m & 127) * 128 + jj * 16));
        *(uint4*)((char*)g_hA + doff) = u16;
    } else if (bx < 8704){
        int t = (bx - 8192) * 256 + tid; // 131072 chunks
        int a = t >> 7, j = t & 127;
        int kc = j >> 3, jj = j & 7;
        float v[8];
        const float* src = W + (size_t)a * 2048 + kc * 64 + jj * 8;
        #pragma unroll
        for (int q = 0; q < 8; ++q) v[q] = src[q];
        uint4 u16 = cvt8(v);
        size_t doff = ((size_t)((a >> 7) * 16 + kc)) * 16384
                    + swz128((uint32_t)((a & 127) * 128 + jj * 16));
        *(uint4*)((char*)g_wB + doff) = u16;
    } else if (bx < 8768){
        int idx = (bx - 8704) * 256 + tid;
        g_beta[idx] = 0.f;
    } else {
        int w = tid >> 5, lane = tid & 31;
        int a = (bx - 8768) * 8 + w;
        const float* Wr = W + (size_t)a * 2048 + 1024;
        float s = 0.f;
        #pragma unroll 4
        for (int k = lane; k < 1024; k += 32) s += Wr[k] * ht[k];
        #pragma unroll
        for (int o = 16; o; o >>= 1) s += __shfl_xor_sync(0xffffffffu, s, o);
        if (lane == 0) g_c[a] = s + b[a];
    }
}

// ---------------- kernel B: warp-specialized bulk-copy fp16 GEMM -----------
// CTA tile 128x128, 288 threads: warps 0-7 consume (4m x 2n, warp 32x64),
// warp 8 = dedicated producer (bulk copies). full[s] (tx, count 1) /
// empty[s] (count 8) mbarrier pairs; NO __syncthreads in the mainloop.
// 3 stages x 32KB = 97KB smem -> 2 CTAs/SM.
#define ATILE   16384
#define BTILE   16384
#define STAGEB  32768
#define NSTAGE  3
#define KSTAGES 16
#define DYN_SMEM (NSTAGE * STAGEB + 1024)

__global__ __launch_bounds__(288, 2)
void beta_mma_kernel(const float* __restrict__ u){
    extern __shared__ __align__(1024) char dyn_sm[];
    __shared__ float cs[128], us[128];
    __shared__ unsigned long long mfull[NSTAGE], mempty[NSTAGE];

    const int tid  = threadIdx.x;
    const int lane = tid & 31;
    const int wid  = tid >> 5;         // 0..8
    const int mb = blockIdx.x;         // 128 m-blocks
    const int nb = blockIdx.y;         // 8 n-blocks
    const uint32_t sb = (smem_u32(dyn_sm) + 1023u) & ~1023u;
    uint32_t fullb[NSTAGE], emptyb[NSTAGE];
    #pragma unroll
    for (int i = 0; i < NSTAGE; ++i){
        fullb[i]  = smem_u32(&mfull[i]);
        emptyb[i] = smem_u32(&mempty[i]);
    }

    if (tid < 128){ cs[tid] = g_c[nb * 128 + tid]; us[tid] = u[nb * 128 + tid]; }
    if (tid == 0){
        #pragma unroll
        for (int i = 0; i < NSTAGE; ++i){ mbar_init(fullb[i], 1); mbar_init(emptyb[i], 8); }
    }
    __syncthreads();   // barriers + cs/us visible to everyone

    if (wid == 8){
        // ---------------- producer warp ----------------
        if (lane == 0){
            const char* srcA = (const char*)g_hA + (size_t)mb * 16 * ATILE;
            const char* srcB = (const char*)g_wB + (size_t)nb * 16 * BTILE;
            int pe[NSTAGE] = {0, 0, 0};
            for (int fs = 0; fs < KSTAGES; ++fs){
                int sl = fs % NSTAGE;
                if (fs >= NSTAGE){ mbar_wait(emptyb[sl], pe[sl]); pe[sl] ^= 1; }
                mbar_expect_tx(fullb[sl], STAGEB);
                bulkcp(sb + sl * STAGEB,         srcA + (size_t)fs * ATILE, ATILE, fullb[sl]);
                bulkcp(sb + sl * STAGEB + ATILE, srcB + (size_t)fs * BTILE, BTILE, fullb[sl]);
            }
        }
        return;   // producer done after issuing all copies
    }

    // ---------------- consumer warps (0..7) ----------------
    const int warp_m = wid & 3;        // 4 warps along m (32 rows each)
    const int warp_n = wid >> 2;       // 2 warps along n (64 cols each)
    const int lr = lane & 15;
    const uint32_t cb0 = ((lane >> 4) & 1) * 16;   // byte offset within 128B row

    float acc[2][8][4];
    #pragma unroll
    for (int im = 0; im < 2; ++im)
        #pragma unroll
        for (int j = 0; j < 8; ++j)
            #pragma unroll
            for (int p = 0; p < 4; ++p) acc[im][j][p] = 0.f;

    int pf[NSTAGE] = {0, 0, 0};
    for (int fs = 0; fs < KSTAGES; ++fs){
        int sl = fs % NSTAGE;
        mbar_wait(fullb[sl], pf[sl]); pf[sl] ^= 1;

        uint32_t st = sb + (uint32_t)sl * STAGEB;
        #pragma unroll
        for (int half = 0; half < 4; ++half){
            const uint32_t cbyte = cb0 + half * 32;
            uint32_t aF[2][4], bW[4][4];
            #pragma unroll
            for (int im = 0; im < 2; ++im){
                uint32_t row = (uint32_t)(warp_m * 32 + im * 16 + lr);
                ldm4(aF[im], st + swz128(row * 128 + cbyte));
            }
            #pragma unroll
            for (int t = 0; t < 4; ++t){
                uint32_t row = (uint32_t)(warp_n * 64 + t * 16 + lr);
                ldm4(bW[t], st + ATILE + swz128(row * 128 + cbyte));
            }
            #pragma unroll
            for (int im = 0; im < 2; ++im)
                #pragma unroll
                for (int i8 = 0; i8 < 8; ++i8){
                    const int t = i8 >> 1, hf = i8 & 1;
                    mma16816(acc[im][i8], aF[im], bW[t][hf], bW[t][hf + 2]);
                }
        }
        __syncwarp();
        if (lane == 0) mbar_arrive(emptyb[sl]);
    }

    // epilogue: tanh(y + c) * u, reduce over n, atomic into g_beta
    #pragma unroll
    for (int im = 0; im < 2; ++im){
        #pragma unroll
        for (int rh = 0; rh < 2; ++rh){
            float p = 0.f;
            #pragma unroll
            for (int i8 = 0; i8 < 8; ++i8){
                int n = warp_n * 64 + i8 * 8 + 2 * (lane & 3);
                float v0 = acc[im][i8][rh * 2 + 0];
                float v1 = acc[im][i8][rh * 2 + 1];
                p += fast_tanh(v0 + cs[n])     * us[n];
                p += fast_tanh(v1 + cs[n + 1]) * us[n + 1];
            }
            p += __shfl_xor_sync(0xffffffffu, p, 1);
            p += __shfl_xor_sync(0xffffffffu, p, 2);
            if ((lane & 3) == 0){
                int row = mb * 128 + warp_m * 32 + im * 16 + rh * 8 + (lane >> 2);
                atomicAdd(&g_beta[row], p);
            }
        }
    }
}

// ---------------- kernel C: softmax reductions + zero output ----------------
__global__ void softmax_kernel(float* __restrict__ out){
    __shared__ float red[32];
    const int tid = threadIdx.x;   // 1024 threads
    float mx = -3.0e38f;
    for (int i = tid; i < LL; i += 1024) mx = fmaxf(mx, g_beta[i]);
    #pragma unroll
    for (int o = 16; o; o >>= 1) mx = fmaxf(mx, __shfl_xor_sync(0xffffffffu, mx, o));
    if ((tid & 31) == 0) red[tid >> 5] = mx;
    __syncthreads();
    if (tid < 32){
        float v = red[tid];
        #pragma unroll
        for (int o = 16; o; o >>= 1) v = fmaxf(v, __shfl_xor_sync(0xffffffffu, v, o));
        if (tid == 0) red[0] = v;
    }
    __syncthreads();
    mx = red[0];
    __syncthreads();

    float s = 0.f;
    for (int i = tid; i < LL; i += 1024) s += __expf(g_beta[i] - mx);
    #pragma unroll
    for (int o = 16; o; o >>= 1) s += __shfl_xor_sync(0xffffffffu, s, o);
    if ((tid & 31) == 0) red[tid >> 5] = s;
    __syncthreads();
    if (tid < 32){
        float v = red[tid];
        #pragma unroll
        for (int o = 16; o; o >>= 1) v += __shfl_xor_sync(0xffffffffu, v, o);
        if (tid == 0){ g_red[0] = mx; g_red[1] = v; }
    }
    out[tid] = 0.f;
}

// ---------------- kernel D: s[d] = sum_i alpha_i * h16[i][d] ----------------
// Reads tiled+swizzled g_hA. grid (4 col-quarters, 128 row-blocks), 256 thr.
// Each thread: contiguous 16-row range, 4 independent loads per unrolled step.
__global__ __launch_bounds__(256)
void wsum_kernel(float* __restrict__ out){
    __shared__ float wsm[128];
    __shared__ float part[8 * 256];
    __shared__ int alive;
    const int tid = threadIdx.x;
    const int i0 = blockIdx.y * 128;           // aligned to 128-row tiles
    if (tid == 0) alive = 0;
    __syncthreads();

    const float mx = g_red[0];
    const float invZ = 1.0f / g_red[1];
    if (tid < 128){
        float bv = g_beta[i0 + tid] - mx;
        if (bv > -30.f) alive = 1;
        wsm[tid] = __expf(bv) * invZ;
    }
    __syncthreads();
    if (!alive) return;

    const int c  = tid & 31;                   // 8-half chunk within quarter
    const int rg = tid >> 5;                   // row group 0..7
    const int col0 = blockIdx.x * 256 + c * 8; // global column
    const int kc = col0 >> 6;                  // k-chunk 0..15
    const uint32_t jbyte = (uint32_t)((col0 & 63) * 2);  // byte offset in row
    const char* tile = (const char*)g_hA + ((size_t)blockIdx.y * 16 + kc) * 16384;
    const int rbase = rg * 16;

    float acc[8];
    #pragma unroll
    for (int k = 0; k < 8; ++k) acc[k] = 0.f;

    #pragma unroll
    for (int ii = 0; ii < 16; ii += 4){
        uint4 v[4];
        #pragma unroll
        for (int q = 0; q < 4; ++q)
            v[q] = *(const uint4*)(tile + swz128((uint32_t)(rbase + ii + q) * 128 + jbyte));
        #pragma unroll
        for (int q = 0; q < 4; ++q){
            float w = wsm[rbase + ii + q];
            const __half2* h2 = (const __half2*)&v[q];
            #pragma unroll
            for (int p = 0; p < 4; ++p){
                float2 f = __half22float2(h2[p]);
                acc[2*p + 0] += w * f.x;
                acc[2*p + 1] += w * f.y;
            }
        }
    }
    #pragma unroll
    for (int k = 0; k < 8; ++k) part[rg * 256 + c * 8 + k] = acc[k];
    __syncthreads();

    float sum = 0.f;
    #pragma unroll
    for (int rg2 = 0; rg2 < 8; ++rg2) sum += part[rg2 * 256 + tid];
    atomicAdd(&out[blockIdx.x * 256 + tid], sum);
}

// ---------------- launch ----------------
extern "C" void kernel_launch(void* const* d_in, const int* in_sizes, int n_in,
                              void* d_out, int out_size){
    const float* h_i   = (const float*)d_in[0];
    const float* h_t   = (const float*)d_in[1];
    const float* W_att = (const float*)d_in[2];
    const float* b_att = (const float*)d_in[3];
    const float* u     = (const float*)d_in[4];
    float* out = (float*)d_out;

    cudaFuncSetAttribute(beta_mma_kernel,
                         cudaFuncAttributeMaxDynamicSharedMemorySize, DYN_SMEM);

    prep_kernel<<<8896, 256>>>(h_i, W_att, h_t, b_att);
    beta_mma_kernel<<<dim3(128, 8), 288, DYN_SMEM>>>(u);
    softmax_kernel<<<1, 1024>>>(out);
    wsum_kernel<<<dim3(4, 128), 256>>>(out);
}

// round 15
// speedup vs baseline: 1.2000x; 1.2000x over previous
#include <cuda_runtime.h>
#include <cuda_fp16.h>
#include <math.h>
#include <stdint.h>

#define LL 16384
#define DD 1024
#define AA 1024

// ---------------- device scratch (static: allocation-free) ----------------
// A: 128 m-blocks x 16 k-chunks, tile 128x64 halves = 16KB, SW128-preswizzled
// B: 8   n-blocks x 16 k-chunks, tile 128x64 halves = 16KB, SW128-preswizzled
__device__ uint4 g_hA[2097152];    // 32 MB
__device__ uint4 g_wB[131072];     // 2 MB
__device__ float g_c[AA];
__device__ float g_beta[LL];
__device__ float g_red[2];         // [0]=max, [1]=sum(exp)

// ---------------- PTX helpers ----------------
__device__ __forceinline__ uint32_t smem_u32(const void* p){
    uint32_t a;
    asm("{ .reg .u64 t; cvta.to.shared.u64 t, %1; cvt.u32.u64 %0, t; }" : "=r"(a) : "l"(p));
    return a;
}
__device__ __forceinline__ uint32_t swz128(uint32_t off){ return off ^ ((off >> 3) & 0x70u); }

__device__ __forceinline__ void mbar_init(uint32_t mbar, uint32_t cnt){
    asm volatile("mbarrier.init.shared.b64 [%0], %1;" :: "r"(mbar), "r"(cnt) : "memory");
}
__device__ __forceinline__ void mbar_expect_tx(uint32_t mbar, uint32_t bytes){
    asm volatile("mbarrier.arrive.expect_tx.shared.b64 _, [%0], %1;"
                 :: "r"(mbar), "r"(bytes) : "memory");
}
__device__ __forceinline__ void mbar_wait(uint32_t mbar, int parity){
    asm volatile(
        "{\n\t.reg .pred P1;\n\t"
        "LAB_WAIT_%=:\n\t"
        "mbarrier.try_wait.parity.acquire.cta.shared::cta.b64 P1, [%0], %1, 0x989680;\n\t"
        "@P1 bra.uni LAB_DONE_%=;\n\t"
        "bra.uni LAB_WAIT_%=;\n\t"
        "LAB_DONE_%=:\n\t}"
        :: "r"(mbar), "r"((uint32_t)parity) : "memory");
}
__device__ __forceinline__ void bulkcp(uint32_t dst, const void* src, uint32_t bytes,
                                       uint32_t mbar){
    asm volatile(
        "cp.async.bulk.shared::cta.global.mbarrier::complete_tx::bytes [%0], [%1], %2, [%3];"
        :: "r"(dst), "l"(src), "r"(bytes), "r"(mbar) : "memory");
}
__device__ __forceinline__ void ldm4(uint32_t* r, uint32_t addr){
    asm volatile("ldmatrix.sync.aligned.m8n8.x4.shared.b16 {%0,%1,%2,%3}, [%4];"
        : "=r"(r[0]), "=r"(r[1]), "=r"(r[2]), "=r"(r[3]) : "r"(addr));
}
__device__ __forceinline__ void mma16816(float* d, const uint32_t* a,
                                         uint32_t b0, uint32_t b1){
    asm volatile(
        "mma.sync.aligned.m16n8k16.row.col.f32.f16.f16.f32 "
        "{%0,%1,%2,%3}, {%4,%5,%6,%7}, {%8,%9}, {%0,%1,%2,%3};"
        : "+f"(d[0]), "+f"(d[1]), "+f"(d[2]), "+f"(d[3])
        : "r"(a[0]), "r"(a[1]), "r"(a[2]), "r"(a[3]), "r"(b0), "r"(b1));
}

__device__ __forceinline__ float fast_tanh(float x){
    float e = __expf(-2.0f * fabsf(x));
    float t = __fdividef(1.0f - e, 1.0f + e);
    return copysignf(t, x);
}

__device__ __forceinline__ uint4 cvt8v(float4 a, float4 b){
    union { __half e[8]; uint4 u; } H;
    H.e[0] = __float2half(a.x); H.e[1] = __float2half(a.y);
    H.e[2] = __float2half(a.z); H.e[3] = __float2half(a.w);
    H.e[4] = __float2half(b.x); H.e[5] = __float2half(b.y);
    H.e[6] = __float2half(b.z); H.e[7] = __float2half(b.w);
    return H.u;
}

// ---------------- prep kernel --------------------------------------------
// blocks [0, 8192)     : h -> fp16 tiled+swizzled g_hA (128x64 tiles)
// blocks [8192, 8704)  : W1 -> fp16 tiled+swizzled g_wB
// blocks [8704, 8768)  : zero g_beta
// blocks [8768, 8896)  : c = W2 @ ht + b
__global__ void prep_kernel(const float* __restrict__ h,
                            const float* __restrict__ W,
                            const float* __restrict__ ht,
                            const float* __restrict__ b){
    const int bx = blockIdx.x, tid = threadIdx.x;
    if (bx < 8192){
        int t = bx * 256 + tid;          // 2M chunks of 8 halves
        int m = t >> 7, j = t & 127;
        int kc = j >> 3, jj = j & 7;
        const float4* src = (const float4*)(h + (size_t)m * 1024 + kc * 64 + jj * 8);
        uint4 u16 = cvt8v(src[0], src[1]);
        size_t doff = ((size_t)((m >> 7) * 16 + kc)) * 16384
                    + swz128((uint32_t)((m & 127) * 128 + jj * 16));
        *(uint4*)((char*)g_hA + doff) = u16;
    } else if (bx < 8704){
        int t = (bx - 8192) * 256 + tid; // 131072 chunks
        int a = t >> 7, j = t & 127;
        int kc = j >> 3, jj = j & 7;
        const float4* src = (const float4*)(W + (size_t)a * 2048 + kc * 64 + jj * 8);
        uint4 u16 = cvt8v(src[0], src[1]);
        size_t doff = ((size_t)((a >> 7) * 16 + kc)) * 16384
                    + swz128((uint32_t)((a & 127) * 128 + jj * 16));
        *(uint4*)((char*)g_wB + doff) = u16;
    } else if (bx < 8768){
        int idx = (bx - 8704) * 256 + tid;
        g_beta[idx] = 0.f;
    } else {
        int w = tid >> 5, lane = tid & 31;
        int a = (bx - 8768) * 8 + w;
        const float* Wr = W + (size_t)a * 2048 + 1024;
        float s = 0.f;
        #pragma unroll 4
        for (int k = lane; k < 1024; k += 32) s += Wr[k] * ht[k];
        #pragma unroll
        for (int o = 16; o; o >>= 1) s += __shfl_xor_sync(0xffffffffu, s, o);
        if (lane == 0) g_c[a] = s + b[a];
    }
}

// ---------------- kernel B: bulk-copy pipelined fp16 mma.sync GEMM ---------
// CTA tile 128x128, 256 threads (8 warps, 4m x 2n), warp tile 32x64.
// K=64 per stage; per stage: sync (slot free proof) -> refill -> wait full
// -> compute. 3 stages x 32KB = 97KB smem -> 2 CTAs/SM.
#define ATILE   16384
#define BTILE   16384
#define STAGEB  32768
#define NSTAGE  3
#define KSTAGES 16
#define DYN_SMEM (NSTAGE * STAGEB + 1024)

__global__ __launch_bounds__(256, 2)
void beta_mma_kernel(const float* __restrict__ u){
    extern __shared__ __align__(1024) char dyn_sm[];
    __shared__ float cs[128], us[128];
    __shared__ unsigned long long mbar[NSTAGE];

    const int tid  = threadIdx.x;
    const int lane = tid & 31;
    const int wid  = tid >> 5;         // 0..7
    const int warp_m = wid & 3;        // 4 warps along m (32 rows each)
    const int warp_n = wid >> 2;       // 2 warps along n (64 cols each)
    const int mb = blockIdx.x;         // 128 m-blocks
    const int nb = blockIdx.y;         // 8 n-blocks
    const uint32_t sb = (smem_u32(dyn_sm) + 1023u) & ~1023u;
    const uint32_t mb0 = smem_u32(&mbar[0]);
    const uint32_t mb1 = smem_u32(&mbar[1]);
    const uint32_t mb2 = smem_u32(&mbar[2]);

    if (tid < 128){ cs[tid] = g_c[nb * 128 + tid]; us[tid] = u[nb * 128 + tid]; }
    if (tid == 0){ mbar_init(mb0, 1); mbar_init(mb1, 1); mbar_init(mb2, 1); }
    __syncthreads();

    const char* srcA = (const char*)g_hA + (size_t)mb * 16 * ATILE;
    const char* srcB = (const char*)g_wB + (size_t)nb * 16 * BTILE;

    if (tid == 0){
        #pragma unroll
        for (int slot = 0; slot < 2; ++slot){
            uint32_t mba = slot ? mb1 : mb0;
            mbar_expect_tx(mba, STAGEB);
            bulkcp(sb + slot * STAGEB,         srcA + (size_t)slot * ATILE, ATILE, mba);
            bulkcp(sb + slot * STAGEB + ATILE, srcB + (size_t)slot * BTILE, BTILE, mba);
        }
    }

    float acc[2][8][4];
    #pragma unroll
    for (int im = 0; im < 2; ++im)
        #pragma unroll
        for (int j = 0; j < 8; ++j)
            #pragma unroll
            for (int p = 0; p < 4; ++p) acc[im][j][p] = 0.f;

    const int lr = lane & 15;
    const uint32_t cb0 = ((lane >> 4) & 1) * 16;   // byte offset within 128B row

    int s = 0, sl = 2;
    int p0 = 0, p1 = 0, p2 = 0;
    for (int kt = 0; kt < KSTAGES; ++kt){
        // slot sl was consumed at iteration kt-1; this sync proves every warp
        // finished with it, so the refill can be issued BEFORE the full-wait.
        __syncthreads();

        if (tid == 0 && kt + 2 < KSTAGES){
            int kc = kt + 2;
            uint32_t mba = (sl == 0) ? mb0 : (sl == 1) ? mb1 : mb2;
            mbar_expect_tx(mba, STAGEB);
            bulkcp(sb + sl * STAGEB,         srcA + (size_t)kc * ATILE, ATILE, mba);
            bulkcp(sb + sl * STAGEB + ATILE, srcB + (size_t)kc * BTILE, BTILE, mba);
        }

        if (s == 0){ mbar_wait(mb0, p0); p0 ^= 1; }
        else if (s == 1){ mbar_wait(mb1, p1); p1 ^= 1; }
        else { mbar_wait(mb2, p2); p2 ^= 1; }

        uint32_t st = sb + (uint32_t)s * STAGEB;
        #pragma unroll
        for (int half = 0; half < 4; ++half){
            const uint32_t cbyte = cb0 + half * 32;
            uint32_t aF[2][4], bW[4][4];
            #pragma unroll
            for (int im = 0; im < 2; ++im){
                uint32_t row = (uint32_t)(warp_m * 32 + im * 16 + lr);
                ldm4(aF[im], st + swz128(row * 128 + cbyte));
            }
            #pragma unroll
            for (int t = 0; t < 4; ++t){
                uint32_t row = (uint32_t)(warp_n * 64 + t * 16 + lr);
                ldm4(bW[t], st + ATILE + swz128(row * 128 + cbyte));
            }
            #pragma unroll
            for (int im = 0; im < 2; ++im)
                #pragma unroll
                for (int i8 = 0; i8 < 8; ++i8){
                    const int t = i8 >> 1, hf = i8 & 1;
                    mma16816(acc[im][i8], aF[im], bW[t][hf], bW[t][hf + 2]);
                }
        }

        s  = (s  == NSTAGE - 1) ? 0 : s + 1;
        sl = (sl == NSTAGE - 1) ? 0 : sl + 1;
    }

    // epilogue: tanh(y + c) * u, reduce over n, atomic into g_beta
    #pragma unroll
    for (int im = 0; im < 2; ++im){
        #pragma unroll
        for (int rh = 0; rh < 2; ++rh){
            float p = 0.f;
            #pragma unroll
            for (int i8 = 0; i8 < 8; ++i8){
                int n = warp_n * 64 + i8 * 8 + 2 * (lane & 3);
                float v0 = acc[im][i8][rh * 2 + 0];
                float v1 = acc[im][i8][rh * 2 + 1];
                p += fast_tanh(v0 + cs[n])     * us[n];
                p += fast_tanh(v1 + cs[n + 1]) * us[n + 1];
            }
            p += __shfl_xor_sync(0xffffffffu, p, 1);
            p += __shfl_xor_sync(0xffffffffu, p, 2);
            if ((lane & 3) == 0){
                int row = mb * 128 + warp_m * 32 + im * 16 + rh * 8 + (lane >> 2);
                atomicAdd(&g_beta[row], p);
            }
        }
    }
}

// ---------------- kernel C: softmax reductions + zero output ----------------
__global__ void softmax_kernel(float* __restrict__ out){
    __shared__ float red[32];
    const int tid = threadIdx.x;   // 1024 threads
    const float4* bp = (const float4*)g_beta;   // 4096 float4s
    float mx = -3.0e38f;
    #pragma unroll
    for (int i = 0; i < 4; ++i){
        float4 v = bp[tid + i * 1024];
        mx = fmaxf(mx, fmaxf(fmaxf(v.x, v.y), fmaxf(v.z, v.w)));
    }
    #pragma unroll
    for (int o = 16; o; o >>= 1) mx = fmaxf(mx, __shfl_xor_sync(0xffffffffu, mx, o));
    if ((tid & 31) == 0) red[tid >> 5] = mx;
    __syncthreads();
    if (tid < 32){
        float v = red[tid];
        #pragma unroll
        for (int o = 16; o; o >>= 1) v = fmaxf(v, __shfl_xor_sync(0xffffffffu, v, o));
        if (tid == 0) red[0] = v;
    }
    __syncthreads();
    mx = red[0];
    __syncthreads();

    float s = 0.f;
    #pragma unroll
    for (int i = 0; i < 4; ++i){
        float4 v = bp[tid + i * 1024];
        s += __expf(v.x - mx) + __expf(v.y - mx) + __expf(v.z - mx) + __expf(v.w - mx);
    }
    #pragma unroll
    for (int o = 16; o; o >>= 1) s += __shfl_xor_sync(0xffffffffu, s, o);
    if ((tid & 31) == 0) red[tid >> 5] = s;
    __syncthreads();
    if (tid < 32){
        float v = red[tid];
        #pragma unroll
        for (int o = 16; o; o >>= 1) v += __shfl_xor_sync(0xffffffffu, v, o);
        if (tid == 0){ g_red[0] = mx; g_red[1] = v; }
    }
    out[tid] = 0.f;
}

// ---------------- kernel D: s[d] = sum_i alpha_i * h16[i][d] ----------------
// Reads tiled+swizzled g_hA. grid (4 col-quarters, 128 row-blocks), 256 thr.
// Each thread: contiguous 16-row range, 4 independent loads per unrolled step.
__global__ __launch_bounds__(256)
void wsum_kernel(float* __restrict__ out){
    __shared__ float wsm[128];
    __shared__ float part[8 * 256];
    __shared__ int alive;
    const int tid = threadIdx.x;
    const int i0 = blockIdx.y * 128;           // aligned to 128-row tiles
    if (tid == 0) alive = 0;
    __syncthreads();

    const float mx = g_red[0];
    const float invZ = 1.0f / g_red[1];
    if (tid < 128){
        float bv = g_beta[i0 + tid] - mx;
        if (bv > -30.f) alive = 1;
        wsm[tid] = __expf(bv) * invZ;
    }
    __syncthreads();
    if (!alive) return;

    const int c  = tid & 31;                   // 8-half chunk within quarter
    const int rg = tid >> 5;                   // row group 0..7
    const int col0 = blockIdx.x * 256 + c * 8; // global column
    const int kc = col0 >> 6;                  // k-chunk 0..15
    const uint32_t jbyte = (uint32_t)((col0 & 63) * 2);  // byte offset in row
    const char* tile = (const char*)g_hA + ((size_t)blockIdx.y * 16 + kc) * 16384;
    const int rbase = rg * 16;

    float acc[8];
    #pragma unroll
    for (int k = 0; k < 8; ++k) acc[k] = 0.f;

    #pragma unroll
    for (int ii = 0; ii < 16; ii += 4){
        uint4 v[4];
        #pragma unroll
        for (int q = 0; q < 4; ++q)
            v[q] = *(const uint4*)(tile + swz128((uint32_t)(rbase + ii + q) * 128 + jbyte));
        #pragma unroll
        for (int q = 0; q < 4; ++q){
            float w = wsm[rbase + ii + q];
            const __half2* h2 = (const __half2*)&v[q];
            #pragma unroll
            for (int p = 0; p < 4; ++p){
                float2 f = __half22float2(h2[p]);
                acc[2*p + 0] += w * f.x;
                acc[2*p + 1] += w * f.y;
            }
        }
    }
    #pragma unroll
    for (int k = 0; k < 8; ++k) part[rg * 256 + c * 8 + k] = acc[k];
    __syncthreads();

    float sum = 0.f;
    #pragma unroll
    for (int rg2 = 0; rg2 < 8; ++rg2) sum += part[rg2 * 256 + tid];
    atomicAdd(&out[blockIdx.x * 256 + tid], sum);
}

// ---------------- launch ----------------
extern "C" void kernel_launch(void* const* d_in, const int* in_sizes, int n_in,
                              void* d_out, int out_size){
    const float* h_i   = (const float*)d_in[0];
    const float* h_t   = (const float*)d_in[1];
    const float* W_att = (const float*)d_in[2];
    const float* b_att = (const float*)d_in[3];
    const float* u     = (const float*)d_in[4];
    float* out = (float*)d_out;

    cudaFuncSetAttribute(beta_mma_kernel,
                         cudaFuncAttributeMaxDynamicSharedMemorySize, DYN_SMEM);

    prep_kernel<<<8896, 256>>>(h_i, W_att, h_t, b_att);
    beta_mma_kernel<<<dim3(128, 8), 256, DYN_SMEM>>>(u);
    softmax_kernel<<<1, 1024>>>(out);
    wsum_kernel<<<dim3(4, 128), 256>>>(out);
}